// round 15
// baseline (speedup 1.0000x reference)
#include <cuda_runtime.h>
#include <cstdint>

#define N_NODES 40000
#define N_EDGES 640000
#define DD 128
#define HH 256

typedef unsigned long long u64;

// ---------------- scratch (static device globals: no allocation) ----------------
__device__ __align__(16) float g_S [(size_t)N_NODES * HH];  // sender_x  @ ew1[0:128]
__device__ __align__(16) float g_R [(size_t)N_NODES * HH];  // receiver_x@ ew1[128:256] + eb1
__device__ __align__(16) float g_RN[(size_t)N_NODES * HH];  // receiver_x@ nw1[0:128]   + nb1
__device__ __align__(16) float g_agg[(size_t)N_NODES * DD]; // scatter sum of edge messages
__device__ float g_cnt[N_NODES];
__device__ int   g_src[N_EDGES];
__device__ int   g_dst[N_EDGES];

// ---------------- f32x2 helpers ----------------
__device__ __forceinline__ u64 fma2(u64 a, u64 b, u64 c) {
    u64 d;
    asm("fma.rn.f32x2 %0, %1, %2, %3;" : "=l"(d) : "l"(a), "l"(b), "l"(c));
    return d;
}
__device__ __forceinline__ u64 pack2(float x, float y) {
    u64 d;
    asm("mov.b64 %0, {%1, %2};" : "=l"(d) : "f"(x), "f"(y));
    return d;
}
__device__ __forceinline__ void unpack2(u64 v, float& x, float& y) {
    asm("mov.b64 {%0, %1}, %2;" : "=f"(x), "=f"(y) : "l"(v));
}
__device__ __forceinline__ float silu_f(float x) {
    return x * (1.0f / (1.0f + __expf(-x)));
}

// ---------------- dtype-robust edge index decode ----------------
__global__ void decode_idx_kernel(const void* __restrict__ raw)
{
    const int* r32 = (const int*)raw;
    bool is64 = ((r32[1] | r32[3] | r32[5] | r32[7]) == 0);
    size_t i = (size_t)blockIdx.x * blockDim.x + threadIdx.x;
    if (i >= N_EDGES) return;
    if (is64) {
        const long long* r64 = (const long long*)raw;
        g_src[i] = (int)r64[i];
        g_dst[i] = (int)r64[(size_t)N_EDGES + i];
    } else {
        g_src[i] = r32[i];
        g_dst[i] = r32[(size_t)N_EDGES + i];
    }
}

// ---------------- GEMM cores (direct-LDG weights, zero barriers) ----------------
// Column ownership: thread lane owns cols {64*j + 2*lane, 64*j + 2*lane + 1}.
// W is read straight from global as coalesced LDG.64 (256B/warp/load), L1/L2
// cached and shared across CTAs. A rows come from smem as broadcast LDS.128.

// C[64,256] += A[64,128] @ W[128,256]
__device__ __forceinline__ void gemm1(const float* __restrict__ Wg,
                                      const float (*__restrict__ sA)[DD],
                                      u64 acc[8][4], int tid)
{
    const int rg = tid >> 5, lane = tid & 31;
    const u64* __restrict__ W64 = (const u64*)Wg;   // 128 u64 per k-row
    for (int ko = 0; ko < 8; ++ko) {
#pragma unroll
        for (int k4 = 0; k4 < 4; ++k4) {
            float4 a4[8];
#pragma unroll
            for (int i = 0; i < 8; i++)
                a4[i] = *(const float4*)&sA[rg * 8 + i][ko * 16 + k4 * 4];
#pragma unroll
            for (int t = 0; t < 4; ++t) {
                const int k = ko * 16 + k4 * 4 + t;
                const u64* wr = W64 + (size_t)k * (HH / 2) + lane;
                u64 w0 = wr[0], w1 = wr[32], w2 = wr[64], w3 = wr[96];
#pragma unroll
                for (int i = 0; i < 8; i++) {
                    float a = (t == 0) ? a4[i].x : (t == 1) ? a4[i].y
                            : (t == 2) ? a4[i].z : a4[i].w;
                    u64 a2 = pack2(a, a);
                    acc[i][0] = fma2(a2, w0, acc[i][0]);
                    acc[i][1] = fma2(a2, w1, acc[i][1]);
                    acc[i][2] = fma2(a2, w2, acc[i][2]);
                    acc[i][3] = fma2(a2, w3, acc[i][3]);
                }
            }
        }
    }
}

// C[64,128] += H[64,256] @ W[256,128]
__device__ __forceinline__ void gemm2(const float* __restrict__ Wg,
                                      const float (*__restrict__ sH)[HH],
                                      u64 acc[8][2], int tid)
{
    const int rg = tid >> 5, lane = tid & 31;
    const u64* __restrict__ W64 = (const u64*)Wg;   // 64 u64 per k-row
    for (int ko = 0; ko < 16; ++ko) {
#pragma unroll
        for (int k4 = 0; k4 < 4; ++k4) {
            float4 a4[8];
#pragma unroll
            for (int i = 0; i < 8; i++)
                a4[i] = *(const float4*)&sH[rg * 8 + i][ko * 16 + k4 * 4];
#pragma unroll
            for (int t = 0; t < 4; ++t) {
                const int k = ko * 16 + k4 * 4 + t;
                const u64* wr = W64 + (size_t)k * (DD / 2) + lane;
                u64 w0 = wr[0], w1 = wr[32];
#pragma unroll
                for (int i = 0; i < 8; i++) {
                    float a = (t == 0) ? a4[i].x : (t == 1) ? a4[i].y
                            : (t == 2) ? a4[i].z : a4[i].w;
                    u64 a2 = pack2(a, a);
                    acc[i][0] = fma2(a2, w0, acc[i][0]);
                    acc[i][1] = fma2(a2, w1, acc[i][1]);
                }
            }
        }
    }
}

// ---------------- phase 1: node-side partial pre-activations ----------------
__global__ __launch_bounds__(256, 2) void prek(
    const float* __restrict__ sx, const float* __restrict__ rx,
    const float* __restrict__ ew1, const float* __restrict__ eb1,
    const float* __restrict__ nw1, const float* __restrict__ nb1)
{
    extern __shared__ char smraw[];
    float (*sA)[DD] = (float(*)[DD])smraw;          // 32 KB

    const int tid = threadIdx.x, rg = tid >> 5, lane = tid & 31;
    const size_t base = (size_t)blockIdx.x * 64;
    const int y = blockIdx.y;
    const float* X    = (y == 0) ? sx : rx;
    const float* W    = (y == 0) ? ew1 : ((y == 1) ? (ew1 + 128 * 256) : nw1);
    const float* bias = (y == 1) ? eb1 : ((y == 2) ? nb1 : nullptr);
    float* out        = (y == 0) ? g_S : ((y == 1) ? g_R : g_RN);

#pragma unroll
    for (int t = 0; t < 8; t++) {
        int f = tid + t * 256;
        ((float4*)sA)[f] = ((const float4*)X)[base * 32 + f];
    }
    __syncthreads();

    u64 acc[8][4];
#pragma unroll
    for (int i = 0; i < 8; i++)
#pragma unroll
        for (int j = 0; j < 4; j++) acc[i][j] = 0ull;

    gemm1(W, sA, acc, tid);

    float2 bb[4];
#pragma unroll
    for (int j = 0; j < 4; j++) {
        if (bias) bb[j] = *(const float2*)(bias + 64 * j + 2 * lane);
        else      bb[j] = make_float2(0.0f, 0.0f);
    }
#pragma unroll
    for (int i = 0; i < 8; i++) {
        int r = rg * 8 + i;
#pragma unroll
        for (int j = 0; j < 4; j++) {
            float v0, v1;
            unpack2(acc[i][j], v0, v1);
            *(float2*)(out + (base + r) * HH + 64 * j + 2 * lane) =
                make_float2(v0 + bb[j].x, v1 + bb[j].y);
        }
    }
}

// ---------------- zero agg/cnt ----------------
__global__ void zero_kernel()
{
    size_t i = (size_t)blockIdx.x * blockDim.x + threadIdx.x;
    const size_t na = (size_t)N_NODES * DD;
    if (i < na) g_agg[i] = 0.0f;
    else if (i < na + N_NODES) g_cnt[i - na] = 0.0f;
}

// ---------------- fused MLP kernel ----------------
// MODE 0: sender; MODE 1: edge (+gather pre, +scatter out); MODE 2: node (agg/cnt in, resid=rx)
template <int MODE>
__global__ __launch_bounds__(256, 2) void fused_mlp_kernel(
    const float* __restrict__ X,
    const float* __restrict__ W1,
    const float* __restrict__ b1,
    const float* __restrict__ W2,
    const float* __restrict__ b2,
    const float* __restrict__ gamma,
    const float* __restrict__ beta,
    const float* __restrict__ resid,
    float* __restrict__ outp)
{
    extern __shared__ char smraw[];
    float (*sA)[DD] = (float(*)[DD])smraw;                      // 32 KB
    float (*sH)[HH] = (float(*)[HH])(smraw + 32768);            // 64 KB
    int*   sSrc     = (int*)(smraw + 32768 + 65536);
    int*   sDst     = sSrc + 64;
    float* sInv     = (float*)(sDst + 64);

    const int tid = threadIdx.x, rg = tid >> 5, lane = tid & 31;
    const size_t base = (size_t)blockIdx.x * 64;

    if (MODE == 1) {
        if (tid < 64) {
            sSrc[tid] = g_src[base + tid];
            sDst[tid] = g_dst[base + tid];
        }
    }

    // ---- load A tile ----
    if (MODE == 2) {
        if (tid < 64) sInv[tid] = 1.0f / fmaxf(g_cnt[base + tid], 1.0f);
        __syncthreads();
#pragma unroll
        for (int t = 0; t < 8; t++) {
            int f = tid + t * 256;
            int r = f >> 5;
            float4 v = ((const float4*)g_agg)[base * 32 + f];
            float inv = sInv[r];
            v.x *= inv; v.y *= inv; v.z *= inv; v.w *= inv;
            ((float4*)sA)[f] = v;
        }
    } else {
#pragma unroll
        for (int t = 0; t < 8; t++) {
            int f = tid + t * 256;
            ((float4*)sA)[f] = ((const float4*)X)[base * 32 + f];
        }
    }
    __syncthreads();

    // ---- GEMM 1 ----
    u64 acc[8][4];
#pragma unroll
    for (int i = 0; i < 8; i++)
#pragma unroll
        for (int j = 0; j < 4; j++) acc[i][j] = 0ull;
    gemm1(W1, sA, acc, tid);

    // ---- epilogue 1: pre-add + SiLU -> sH ----
    float2 bb[4];
    if (MODE == 0) {
#pragma unroll
        for (int j = 0; j < 4; j++) bb[j] = *(const float2*)(b1 + 64 * j + 2 * lane);
    }
#pragma unroll
    for (int i = 0; i < 8; i++) {
        int r = rg * 8 + i;
        float v[8];
#pragma unroll
        for (int j = 0; j < 4; j++) unpack2(acc[i][j], v[2 * j], v[2 * j + 1]);
        if (MODE == 0) {
#pragma unroll
            for (int j = 0; j < 4; j++) { v[2 * j] += bb[j].x; v[2 * j + 1] += bb[j].y; }
        } else if (MODE == 1) {
            const float* Sp = g_S + (size_t)sSrc[r] * HH + 2 * lane;
            const float* Rp = g_R + (size_t)sDst[r] * HH + 2 * lane;
#pragma unroll
            for (int j = 0; j < 4; j++) {
                float2 s = *(const float2*)(Sp + 64 * j);
                float2 q = *(const float2*)(Rp + 64 * j);
                v[2 * j]     += s.x + q.x;
                v[2 * j + 1] += s.y + q.y;
            }
        } else {
            const float* Pp = g_RN + (base + r) * HH + 2 * lane;
#pragma unroll
            for (int j = 0; j < 4; j++) {
                float2 p = *(const float2*)(Pp + 64 * j);
                v[2 * j]     += p.x;
                v[2 * j + 1] += p.y;
            }
        }
#pragma unroll
        for (int j = 0; j < 4; j++) {
            float s0 = silu_f(v[2 * j]), s1 = silu_f(v[2 * j + 1]);
            *(float2*)(&sH[r][64 * j + 2 * lane]) = make_float2(s0, s1);
        }
    }
    __syncthreads();   // sH writes (cross-lane) must be visible before gemm2 reads

    // ---- GEMM 2 ----
    u64 acc2[8][2];
#pragma unroll
    for (int i = 0; i < 8; i++) { acc2[i][0] = 0ull; acc2[i][1] = 0ull; }
    gemm2(W2, sH, acc2, tid);

    // ---- epilogue 2: +b2, LayerNorm(128), residual, store (+ scatter) ----
    float2 g2a  = *(const float2*)(gamma + 2 * lane);
    float2 g2b  = *(const float2*)(gamma + 64 + 2 * lane);
    float2 bt2a = *(const float2*)(beta + 2 * lane);
    float2 bt2b = *(const float2*)(beta + 64 + 2 * lane);
    float2 b2a  = *(const float2*)(b2 + 2 * lane);
    float2 b2b  = *(const float2*)(b2 + 64 + 2 * lane);
#pragma unroll
    for (int i = 0; i < 8; i++) {
        int r = rg * 8 + i;
        float y0, y1, y2, y3;
        unpack2(acc2[i][0], y0, y1);
        unpack2(acc2[i][1], y2, y3);
        y0 += b2a.x; y1 += b2a.y; y2 += b2b.x; y3 += b2b.y;
        float s = y0 + y1 + y2 + y3;
        float q = y0 * y0 + y1 * y1 + y2 * y2 + y3 * y3;
#pragma unroll
        for (int off = 16; off > 0; off >>= 1) {
            s += __shfl_xor_sync(0xffffffffu, s, off);
            q += __shfl_xor_sync(0xffffffffu, q, off);
        }
        float mu   = s * (1.0f / 128.0f);
        float var  = q * (1.0f / 128.0f) - mu * mu;
        float rstd = rsqrtf(var + 1e-5f);
        float p0 = (y0 - mu) * rstd * g2a.x + bt2a.x;
        float p1 = (y1 - mu) * rstd * g2a.y + bt2a.y;
        float p2 = (y2 - mu) * rstd * g2b.x + bt2b.x;
        float p3 = (y3 - mu) * rstd * g2b.y + bt2b.y;

        float2 a0, a1;
        if (MODE == 2) {
            a0 = *(const float2*)(resid + (base + r) * DD + 2 * lane);
            a1 = *(const float2*)(resid + (base + r) * DD + 64 + 2 * lane);
        } else {
            a0 = *(const float2*)(&sA[r][2 * lane]);
            a1 = *(const float2*)(&sA[r][64 + 2 * lane]);
        }
        *(float2*)(outp + (base + r) * DD + 2 * lane)      = make_float2(a0.x + p0, a0.y + p1);
        *(float2*)(outp + (base + r) * DD + 64 + 2 * lane) = make_float2(a1.x + p2, a1.y + p3);

        if (MODE == 1) {
            float* ap = g_agg + (size_t)sDst[r] * DD;
            asm volatile("red.global.add.v2.f32 [%0], {%1, %2};"
                         :: "l"(ap + 2 * lane), "f"(p0), "f"(p1) : "memory");
            asm volatile("red.global.add.v2.f32 [%0], {%1, %2};"
                         :: "l"(ap + 64 + 2 * lane), "f"(p2), "f"(p3) : "memory");
            if (lane == 0) atomicAdd(&g_cnt[sDst[r]], 1.0f);
        }
    }
}

// ---------------- launch ----------------
extern "C" void kernel_launch(void* const* d_in, const int* in_sizes, int n_in,
                              void* d_out, int out_size)
{
    (void)in_sizes; (void)n_in; (void)out_size;
    const float* sx  = (const float*)d_in[0];
    const float* rx  = (const float*)d_in[1];
    const float* ea  = (const float*)d_in[2];
    const void*  eix = d_in[3];
    const float* ew1 = (const float*)d_in[4];  const float* eb1 = (const float*)d_in[5];
    const float* ew2 = (const float*)d_in[6];  const float* eb2 = (const float*)d_in[7];
    const float* eg  = (const float*)d_in[8];  const float* ebt = (const float*)d_in[9];
    const float* nw1 = (const float*)d_in[10]; const float* nb1 = (const float*)d_in[11];
    const float* nw2 = (const float*)d_in[12]; const float* nb2 = (const float*)d_in[13];
    const float* ng  = (const float*)d_in[14]; const float* nbt = (const float*)d_in[15];
    const float* sw1 = (const float*)d_in[16]; const float* sb1 = (const float*)d_in[17];
    const float* sw2 = (const float*)d_in[18]; const float* sb2 = (const float*)d_in[19];
    const float* sg  = (const float*)d_in[20]; const float* sbt = (const float*)d_in[21];
    float* out = (float*)d_out;

    const int SM_MAIN = 32768 + 65536 + 1024;   // sA + sH + idx
    const int SM_PRE  = 32768;                  // sA

    static int attr_done = 0;
    if (!attr_done) {
        cudaFuncSetAttribute(prek, cudaFuncAttributeMaxDynamicSharedMemorySize, SM_PRE);
        cudaFuncSetAttribute(fused_mlp_kernel<0>, cudaFuncAttributeMaxDynamicSharedMemorySize, SM_MAIN);
        cudaFuncSetAttribute(fused_mlp_kernel<1>, cudaFuncAttributeMaxDynamicSharedMemorySize, SM_MAIN);
        cudaFuncSetAttribute(fused_mlp_kernel<2>, cudaFuncAttributeMaxDynamicSharedMemorySize, SM_MAIN);
        attr_done = 1;
    }

    // 0) decode edge indices (dtype-robust int64/int32)
    decode_idx_kernel<<<(N_EDGES + 255) / 256, 256>>>(eix);
    // 1) zero scatter buffers
    {
        size_t total = (size_t)N_NODES * DD + N_NODES;
        int blocks = (int)((total + 255) / 256);
        zero_kernel<<<blocks, 256>>>();
    }
    // 2) node-side partial pre-activations (S, R, RN)
    prek<<<dim3(N_NODES / 64, 3), 256, SM_PRE>>>(sx, rx, ew1, eb1, nw1, nb1);
    // 3) sender MLP
    fused_mlp_kernel<0><<<N_NODES / 64, 256, SM_MAIN>>>(
        sx, sw1, sb1, sw2, sb2, sg, sbt, nullptr, out);
    // 4) edge MLP + residual + scatter  (edge part of ew1 = rows 256..383)
    fused_mlp_kernel<1><<<N_EDGES / 64, 256, SM_MAIN>>>(
        ea, ew1 + 256 * 256, nullptr, ew2, eb2, eg, ebt, nullptr,
        out + (size_t)2 * N_NODES * DD);
    // 5) node MLP + residual (aggr part of nw1 = rows 128..255)
    fused_mlp_kernel<2><<<N_NODES / 64, 256, SM_MAIN>>>(
        nullptr, nw1 + 128 * 256, nullptr, nw2, nb2, ng, nbt, rx,
        out + (size_t)N_NODES * DD);
}

// round 16
// speedup vs baseline: 1.0977x; 1.0977x over previous
#include <cuda_runtime.h>
#include <cstdint>

#define N_NODES 40000
#define N_EDGES 640000
#define DD 128
#define HH 256

typedef unsigned long long u64;

// ---------------- scratch (static device globals: no allocation) ----------------
__device__ __align__(16) float g_S [(size_t)N_NODES * HH];  // sender_x  @ ew1[0:128]
__device__ __align__(16) float g_R [(size_t)N_NODES * HH];  // receiver_x@ ew1[128:256] + eb1
__device__ __align__(16) float g_RN[(size_t)N_NODES * HH];  // receiver_x@ nw1[0:128]   + nb1
__device__ __align__(16) float g_agg[(size_t)N_NODES * DD]; // scatter sum of edge messages
__device__ float g_cnt[N_NODES];
__device__ int   g_src[N_EDGES];
__device__ int   g_dst[N_EDGES];

// ---------------- f32x2 helpers ----------------
__device__ __forceinline__ u64 fma2(u64 a, u64 b, u64 c) {
    u64 d;
    asm("fma.rn.f32x2 %0, %1, %2, %3;" : "=l"(d) : "l"(a), "l"(b), "l"(c));
    return d;
}
__device__ __forceinline__ u64 pack2(float x, float y) {
    u64 d;
    asm("mov.b64 %0, {%1, %2};" : "=l"(d) : "f"(x), "f"(y));
    return d;
}
__device__ __forceinline__ void unpack2(u64 v, float& x, float& y) {
    asm("mov.b64 {%0, %1}, %2;" : "=f"(x), "=f"(y) : "l"(v));
}
__device__ __forceinline__ float silu_f(float x) {
    return x * (1.0f / (1.0f + __expf(-x)));
}

// ---------------- cp.async helpers ----------------
__device__ __forceinline__ uint32_t s2u(const void* p) {
    return (uint32_t)__cvta_generic_to_shared(p);
}
__device__ __forceinline__ void cp16(uint32_t s, const void* g) {
    asm volatile("cp.async.cg.shared.global [%0], [%1], 16;" :: "r"(s), "l"(g));
}
__device__ __forceinline__ void cp_commit() {
    asm volatile("cp.async.commit_group;");
}
template <int N>
__device__ __forceinline__ void cp_wait() {
    asm volatile("cp.async.wait_group %0;" :: "n"(N));
}

// ---------------- dtype-robust edge index decode ----------------
__global__ void decode_idx_kernel(const void* __restrict__ raw)
{
    const int* r32 = (const int*)raw;
    bool is64 = ((r32[1] | r32[3] | r32[5] | r32[7]) == 0);
    size_t i = (size_t)blockIdx.x * blockDim.x + threadIdx.x;
    if (i >= N_EDGES) return;
    if (is64) {
        const long long* r64 = (const long long*)raw;
        g_src[i] = (int)r64[i];
        g_dst[i] = (int)r64[(size_t)N_EDGES + i];
    } else {
        g_src[i] = r32[i];
        g_dst[i] = r32[(size_t)N_EDGES + i];
    }
}

// ---------------- GEMM cores: smem-staged W via cp.async 3-stage ring ----------------
// Column ownership: lane owns cols {64*j + 2*lane, +1} -> conflict-free LDS.64.
// One __syncthreads per chunk; copies overlap a full chunk of FMA.

#define G1_CHUNK_K 16
#define G1_CB (G1_CHUNK_K * HH * 4)      // 16384 B
#define G1_NCH 8
#define G2_CHUNK_K 16
#define G2_CB (G2_CHUNK_K * DD * 4)      // 8192 B
#define G2_NCH 16

__device__ __forceinline__ void g1_issue(const float* __restrict__ Wg, uint32_t ring,
                                         int stage, int ch, int tid)
{
    const char* g = (const char*)(Wg + (size_t)ch * G1_CHUNK_K * HH) + tid * 16;
    uint32_t s = ring + stage * G1_CB + tid * 16;
#pragma unroll
    for (int q = 0; q < 4; q++) cp16(s + q * 4096, g + q * 4096);
    cp_commit();
}

// C[64,256] += A[64,128] @ W[128,256]
__device__ __forceinline__ void gemm1(const float* __restrict__ Wg,
                                      const float (*__restrict__ sA)[DD],
                                      float* __restrict__ ringp,
                                      u64 acc[8][4], int tid)
{
    const int rg = tid >> 5, lane = tid & 31;
    const uint32_t ring = s2u(ringp);
    g1_issue(Wg, ring, 0, 0, tid);
    g1_issue(Wg, ring, 1, 1, tid);
    for (int ch = 0; ch < G1_NCH; ++ch) {
        if (ch == G1_NCH - 1) cp_wait<0>(); else cp_wait<1>();
        __syncthreads();
        if (ch + 2 < G1_NCH) g1_issue(Wg, ring, (ch + 2) % 3, ch + 2, tid);
        const float* sW = ringp + (ch % 3) * (G1_CB / 4);
#pragma unroll
        for (int k4 = 0; k4 < 4; ++k4) {
            float4 a4[8];
#pragma unroll
            for (int i = 0; i < 8; i++)
                a4[i] = *(const float4*)&sA[rg * 8 + i][ch * 16 + k4 * 4];
#pragma unroll
            for (int t = 0; t < 4; ++t) {
                const u64* wr = (const u64*)(sW + (k4 * 4 + t) * HH) + lane;
                u64 w0 = wr[0], w1 = wr[32], w2 = wr[64], w3 = wr[96];
#pragma unroll
                for (int i = 0; i < 8; i++) {
                    float a = (t == 0) ? a4[i].x : (t == 1) ? a4[i].y
                            : (t == 2) ? a4[i].z : a4[i].w;
                    u64 a2 = pack2(a, a);
                    acc[i][0] = fma2(a2, w0, acc[i][0]);
                    acc[i][1] = fma2(a2, w1, acc[i][1]);
                    acc[i][2] = fma2(a2, w2, acc[i][2]);
                    acc[i][3] = fma2(a2, w3, acc[i][3]);
                }
            }
        }
    }
    __syncthreads();   // protect ring region before caller reuses it
}

__device__ __forceinline__ void g2_issue(const float* __restrict__ Wg, uint32_t ring,
                                         int stage, int ch, int tid)
{
    const char* g = (const char*)(Wg + (size_t)ch * G2_CHUNK_K * DD) + tid * 16;
    uint32_t s = ring + stage * G2_CB + tid * 16;
#pragma unroll
    for (int q = 0; q < 2; q++) cp16(s + q * 4096, g + q * 4096);
    cp_commit();
}

// C[64,128] += H[64,256] @ W[256,128]
__device__ __forceinline__ void gemm2(const float* __restrict__ Wg,
                                      const float (*__restrict__ sH)[HH],
                                      float* __restrict__ ringp,
                                      u64 acc[8][2], int tid)
{
    const int rg = tid >> 5, lane = tid & 31;
    const uint32_t ring = s2u(ringp);
    g2_issue(Wg, ring, 0, 0, tid);
    g2_issue(Wg, ring, 1, 1, tid);
    for (int ch = 0; ch < G2_NCH; ++ch) {
        if (ch == G2_NCH - 1) cp_wait<0>(); else cp_wait<1>();
        __syncthreads();
        if (ch + 2 < G2_NCH) g2_issue(Wg, ring, (ch + 2) % 3, ch + 2, tid);
        const float* sW = ringp + (ch % 3) * (G2_CB / 4);
#pragma unroll
        for (int k4 = 0; k4 < 4; ++k4) {
            float4 a4[8];
#pragma unroll
            for (int i = 0; i < 8; i++)
                a4[i] = *(const float4*)&sH[rg * 8 + i][ch * 16 + k4 * 4];
#pragma unroll
            for (int t = 0; t < 4; ++t) {
                const u64* wr = (const u64*)(sW + (k4 * 4 + t) * DD) + lane;
                u64 w0 = wr[0], w1 = wr[32];
#pragma unroll
                for (int i = 0; i < 8; i++) {
                    float a = (t == 0) ? a4[i].x : (t == 1) ? a4[i].y
                            : (t == 2) ? a4[i].z : a4[i].w;
                    u64 a2 = pack2(a, a);
                    acc[i][0] = fma2(a2, w0, acc[i][0]);
                    acc[i][1] = fma2(a2, w1, acc[i][1]);
                }
            }
        }
    }
}

// ---------------- phase 1: node-side partial pre-activations ----------------
__global__ __launch_bounds__(256, 2) void prek(
    const float* __restrict__ sx, const float* __restrict__ rx,
    const float* __restrict__ ew1, const float* __restrict__ eb1,
    const float* __restrict__ nw1, const float* __restrict__ nb1)
{
    extern __shared__ char smraw[];
    float (*sA)[DD] = (float(*)[DD])smraw;          // 32 KB
    float* ring = (float*)(smraw + 32768);          // 48 KB ring

    const int tid = threadIdx.x, rg = tid >> 5, lane = tid & 31;
    const size_t base = (size_t)blockIdx.x * 64;
    const int y = blockIdx.y;
    const float* X    = (y == 0) ? sx : rx;
    const float* W    = (y == 0) ? ew1 : ((y == 1) ? (ew1 + 128 * 256) : nw1);
    const float* bias = (y == 1) ? eb1 : ((y == 2) ? nb1 : nullptr);
    float* out        = (y == 0) ? g_S : ((y == 1) ? g_R : g_RN);

#pragma unroll
    for (int t = 0; t < 8; t++) {
        int f = tid + t * 256;
        ((float4*)sA)[f] = ((const float4*)X)[base * 32 + f];
    }
    __syncthreads();

    u64 acc[8][4];
#pragma unroll
    for (int i = 0; i < 8; i++)
#pragma unroll
        for (int j = 0; j < 4; j++) acc[i][j] = 0ull;

    gemm1(W, sA, ring, acc, tid);

    float2 bb[4];
#pragma unroll
    for (int j = 0; j < 4; j++) {
        if (bias) bb[j] = *(const float2*)(bias + 64 * j + 2 * lane);
        else      bb[j] = make_float2(0.0f, 0.0f);
    }
#pragma unroll
    for (int i = 0; i < 8; i++) {
        int r = rg * 8 + i;
#pragma unroll
        for (int j = 0; j < 4; j++) {
            float v0, v1;
            unpack2(acc[i][j], v0, v1);
            *(float2*)(out + (base + r) * HH + 64 * j + 2 * lane) =
                make_float2(v0 + bb[j].x, v1 + bb[j].y);
        }
    }
}

// ---------------- zero agg/cnt ----------------
__global__ void zero_kernel()
{
    size_t i = (size_t)blockIdx.x * blockDim.x + threadIdx.x;
    const size_t na = (size_t)N_NODES * DD;
    if (i < na) g_agg[i] = 0.0f;
    else if (i < na + N_NODES) g_cnt[i - na] = 0.0f;
}

// ---------------- fused MLP kernel ----------------
// MODE 0: sender; MODE 1: edge (+gather pre, +scatter out); MODE 2: node (agg/cnt in)
// Residual is re-read from global (resid ptr) in epilogue-2 for ALL modes.
template <int MODE>
__global__ __launch_bounds__(256, 2) void fused_mlp_kernel(
    const float* __restrict__ X,
    const float* __restrict__ W1,
    const float* __restrict__ b1,
    const float* __restrict__ W2,
    const float* __restrict__ b2,
    const float* __restrict__ gamma,
    const float* __restrict__ beta,
    const float* __restrict__ resid,
    float* __restrict__ outp)
{
    extern __shared__ char smraw[];
    float (*sA)[DD] = (float(*)[DD])smraw;                      // 32 KB (gemm2 ring aliases)
    float (*sH)[HH] = (float(*)[HH])(smraw + 32768);            // 64 KB (gemm1 ring aliases first 48 KB)
    float* ring1    = (float*)(smraw + 32768);
    float* ring2    = (float*)smraw;
    int*   sSrc     = (int*)(smraw + 32768 + 65536);
    int*   sDst     = sSrc + 64;
    float* sInv     = (float*)(sDst + 64);

    const int tid = threadIdx.x, rg = tid >> 5, lane = tid & 31;
    const size_t base = (size_t)blockIdx.x * 64;

    if (MODE == 1) {
        if (tid < 64) {
            sSrc[tid] = g_src[base + tid];
            sDst[tid] = g_dst[base + tid];
        }
    }

    // ---- load A tile ----
    if (MODE == 2) {
        if (tid < 64) sInv[tid] = 1.0f / fmaxf(g_cnt[base + tid], 1.0f);
        __syncthreads();
#pragma unroll
        for (int t = 0; t < 8; t++) {
            int f = tid + t * 256;
            int r = f >> 5;
            float4 v = ((const float4*)g_agg)[base * 32 + f];
            float inv = sInv[r];
            v.x *= inv; v.y *= inv; v.z *= inv; v.w *= inv;
            ((float4*)sA)[f] = v;
        }
    } else {
#pragma unroll
        for (int t = 0; t < 8; t++) {
            int f = tid + t * 256;
            ((float4*)sA)[f] = ((const float4*)X)[base * 32 + f];
        }
    }
    __syncthreads();

    // ---- GEMM 1 (W1 streamed through ring aliased in sH) ----
    u64 acc[8][4];
#pragma unroll
    for (int i = 0; i < 8; i++)
#pragma unroll
        for (int j = 0; j < 4; j++) acc[i][j] = 0ull;
    gemm1(W1, sA, ring1, acc, tid);
    // gemm1 ends with __syncthreads -> safe to write sH now

    // ---- epilogue 1: pre-add + SiLU -> sH ----
    float2 bb[4];
    if (MODE == 0) {
#pragma unroll
        for (int j = 0; j < 4; j++) bb[j] = *(const float2*)(b1 + 64 * j + 2 * lane);
    }
#pragma unroll
    for (int i = 0; i < 8; i++) {
        int r = rg * 8 + i;
        float v[8];
#pragma unroll
        for (int j = 0; j < 4; j++) unpack2(acc[i][j], v[2 * j], v[2 * j + 1]);
        if (MODE == 0) {
#pragma unroll
            for (int j = 0; j < 4; j++) { v[2 * j] += bb[j].x; v[2 * j + 1] += bb[j].y; }
        } else if (MODE == 1) {
            const float* Sp = g_S + (size_t)sSrc[r] * HH + 2 * lane;
            const float* Rp = g_R + (size_t)sDst[r] * HH + 2 * lane;
#pragma unroll
            for (int j = 0; j < 4; j++) {
                float2 s = *(const float2*)(Sp + 64 * j);
                float2 q = *(const float2*)(Rp + 64 * j);
                v[2 * j]     += s.x + q.x;
                v[2 * j + 1] += s.y + q.y;
            }
        } else {
            const float* Pp = g_RN + (base + r) * HH + 2 * lane;
#pragma unroll
            for (int j = 0; j < 4; j++) {
                float2 p = *(const float2*)(Pp + 64 * j);
                v[2 * j]     += p.x;
                v[2 * j + 1] += p.y;
            }
        }
#pragma unroll
        for (int j = 0; j < 4; j++) {
            float s0 = silu_f(v[2 * j]), s1 = silu_f(v[2 * j + 1]);
            *(float2*)(&sH[r][64 * j + 2 * lane]) = make_float2(s0, s1);
        }
    }
    __syncthreads();   // sH visible to all; sA now dead -> gemm2 ring may clobber it

    // ---- GEMM 2 (W2 streamed through ring aliased in sA) ----
    u64 acc2[8][2];
#pragma unroll
    for (int i = 0; i < 8; i++) { acc2[i][0] = 0ull; acc2[i][1] = 0ull; }
    gemm2(W2, sH, ring2, acc2, tid);

    // ---- epilogue 2: +b2, LayerNorm(128), residual (global), store (+ scatter) ----
    float2 g2a  = *(const float2*)(gamma + 2 * lane);
    float2 g2b  = *(const float2*)(gamma + 64 + 2 * lane);
    float2 bt2a = *(const float2*)(beta + 2 * lane);
    float2 bt2b = *(const float2*)(beta + 64 + 2 * lane);
    float2 b2a  = *(const float2*)(b2 + 2 * lane);
    float2 b2b  = *(const float2*)(b2 + 64 + 2 * lane);
#pragma unroll
    for (int i = 0; i < 8; i++) {
        int r = rg * 8 + i;
        float y0, y1, y2, y3;
        unpack2(acc2[i][0], y0, y1);
        unpack2(acc2[i][1], y2, y3);
        y0 += b2a.x; y1 += b2a.y; y2 += b2b.x; y3 += b2b.y;
        float s = y0 + y1 + y2 + y3;
        float q = y0 * y0 + y1 * y1 + y2 * y2 + y3 * y3;
#pragma unroll
        for (int off = 16; off > 0; off >>= 1) {
            s += __shfl_xor_sync(0xffffffffu, s, off);
            q += __shfl_xor_sync(0xffffffffu, q, off);
        }
        float mu   = s * (1.0f / 128.0f);
        float var  = q * (1.0f / 128.0f) - mu * mu;
        float rstd = rsqrtf(var + 1e-5f);
        float p0 = (y0 - mu) * rstd * g2a.x + bt2a.x;
        float p1 = (y1 - mu) * rstd * g2a.y + bt2a.y;
        float p2 = (y2 - mu) * rstd * g2b.x + bt2b.x;
        float p3 = (y3 - mu) * rstd * g2b.y + bt2b.y;

        float2 a0 = *(const float2*)(resid + (base + r) * DD + 2 * lane);
        float2 a1 = *(const float2*)(resid + (base + r) * DD + 64 + 2 * lane);
        *(float2*)(outp + (base + r) * DD + 2 * lane)      = make_float2(a0.x + p0, a0.y + p1);
        *(float2*)(outp + (base + r) * DD + 64 + 2 * lane) = make_float2(a1.x + p2, a1.y + p3);

        if (MODE == 1) {
            float* ap = g_agg + (size_t)sDst[r] * DD;
            asm volatile("red.global.add.v2.f32 [%0], {%1, %2};"
                         :: "l"(ap + 2 * lane), "f"(p0), "f"(p1) : "memory");
            asm volatile("red.global.add.v2.f32 [%0], {%1, %2};"
                         :: "l"(ap + 64 + 2 * lane), "f"(p2), "f"(p3) : "memory");
            if (lane == 0) atomicAdd(&g_cnt[sDst[r]], 1.0f);
        }
    }
}

// ---------------- launch ----------------
extern "C" void kernel_launch(void* const* d_in, const int* in_sizes, int n_in,
                              void* d_out, int out_size)
{
    (void)in_sizes; (void)n_in; (void)out_size;
    const float* sx  = (const float*)d_in[0];
    const float* rx  = (const float*)d_in[1];
    const float* ea  = (const float*)d_in[2];
    const void*  eix = d_in[3];
    const float* ew1 = (const float*)d_in[4];  const float* eb1 = (const float*)d_in[5];
    const float* ew2 = (const float*)d_in[6];  const float* eb2 = (const float*)d_in[7];
    const float* eg  = (const float*)d_in[8];  const float* ebt = (const float*)d_in[9];
    const float* nw1 = (const float*)d_in[10]; const float* nb1 = (const float*)d_in[11];
    const float* nw2 = (const float*)d_in[12]; const float* nb2 = (const float*)d_in[13];
    const float* ng  = (const float*)d_in[14]; const float* nbt = (const float*)d_in[15];
    const float* sw1 = (const float*)d_in[16]; const float* sb1 = (const float*)d_in[17];
    const float* sw2 = (const float*)d_in[18]; const float* sb2 = (const float*)d_in[19];
    const float* sg  = (const float*)d_in[20]; const float* sbt = (const float*)d_in[21];
    float* out = (float*)d_out;

    const int SM_MAIN = 32768 + 65536 + 1024;   // sA + sH(+rings aliased) + idx = 97 KB
    const int SM_PRE  = 32768 + 49152;          // sA + ring = 80 KB

    static int attr_done = 0;
    if (!attr_done) {
        cudaFuncSetAttribute(prek, cudaFuncAttributeMaxDynamicSharedMemorySize, SM_PRE);
        cudaFuncSetAttribute(fused_mlp_kernel<0>, cudaFuncAttributeMaxDynamicSharedMemorySize, SM_MAIN);
        cudaFuncSetAttribute(fused_mlp_kernel<1>, cudaFuncAttributeMaxDynamicSharedMemorySize, SM_MAIN);
        cudaFuncSetAttribute(fused_mlp_kernel<2>, cudaFuncAttributeMaxDynamicSharedMemorySize, SM_MAIN);
        attr_done = 1;
    }

    // 0) decode edge indices (dtype-robust int64/int32)
    decode_idx_kernel<<<(N_EDGES + 255) / 256, 256>>>(eix);
    // 1) zero scatter buffers
    {
        size_t total = (size_t)N_NODES * DD + N_NODES;
        int blocks = (int)((total + 255) / 256);
        zero_kernel<<<blocks, 256>>>();
    }
    // 2) node-side partial pre-activations (S, R, RN)
    prek<<<dim3(N_NODES / 64, 3), 256, SM_PRE>>>(sx, rx, ew1, eb1, nw1, nb1);
    // 3) sender MLP
    fused_mlp_kernel<0><<<N_NODES / 64, 256, SM_MAIN>>>(
        sx, sw1, sb1, sw2, sb2, sg, sbt, sx, out);
    // 4) edge MLP + residual + scatter  (edge part of ew1 = rows 256..383)
    fused_mlp_kernel<1><<<N_EDGES / 64, 256, SM_MAIN>>>(
        ea, ew1 + 256 * 256, nullptr, ew2, eb2, eg, ebt, ea,
        out + (size_t)2 * N_NODES * DD);
    // 5) node MLP + residual (aggr part of nw1 = rows 128..255)
    fused_mlp_kernel<2><<<N_NODES / 64, 256, SM_MAIN>>>(
        nullptr, nw1 + 128 * 256, nullptr, nw2, nb2, ng, nbt, rx,
        out + (size_t)N_NODES * DD);
}